// round 13
// baseline (speedup 1.0000x reference)
#include <cuda_runtime.h>
#include <cuda_bf16.h>
#include <cstdint>
#include <math.h>

#define B_    8
#define S_    1024
#define HID_  1024
#define H_    8
#define HD_   128
#define MD_   8
#define L_    3
#define M_    (B_*S_)
#define BH_   (B_*H_)
#define EPS_  1e-7f
#define INV_SQRT_D 0.08838834764831845f

// ---------------- PTX helpers (plain sm_80+ features only) ----------------
__device__ __forceinline__ uint32_t smem_u32(const void* p){
    uint32_t a;
    asm("{ .reg .u64 t; cvta.to.shared.u64 t, %1; cvt.u32.u64 %0, t; }" : "=r"(a) : "l"(p));
    return a;
}
#define CPA(sa, gp) \
    asm volatile("cp.async.cg.shared.global [%0], [%1], 16;" \
        :: "r"(sa), "l"(__cvta_generic_to_global((const void*)(gp))) : "memory")
#define CP_COMMIT() asm volatile("cp.async.commit_group;" ::: "memory")
#define CP_WAIT2()  asm volatile("cp.async.wait_group 2;" ::: "memory")
#define CP_WAIT1()  asm volatile("cp.async.wait_group 1;" ::: "memory")
#define CP_WAIT0()  asm volatile("cp.async.wait_group 0;" ::: "memory")

#define LDSM4(r, addr) \
    asm volatile("ldmatrix.sync.aligned.m8n8.x4.shared.b16 {%0,%1,%2,%3}, [%4];" \
        : "=r"((r)[0]), "=r"((r)[1]), "=r"((r)[2]), "=r"((r)[3]) : "r"(addr))

#define MMA_B16(c, a0,a1,a2,a3, b0,b1) \
    asm volatile("mma.sync.aligned.m16n8k16.row.col.f32.bf16.bf16.f32 " \
        "{%0,%1,%2,%3}, {%4,%5,%6,%7}, {%8,%9}, {%0,%1,%2,%3};" \
        : "+f"((c)[0]), "+f"((c)[1]), "+f"((c)[2]), "+f"((c)[3]) \
        : "r"(a0), "r"(a1), "r"(a2), "r"(a3), "r"(b0), "r"(b1))

__device__ __forceinline__ uint32_t pack_bf2(float a, float b){
    __nv_bfloat162 t = __floats2bfloat162_rn(a, b);
    return *(uint32_t*)&t;
}

// ---------------- scratch ----------------
__device__ float          g_cur [(size_t)M_ * HID_];
__device__ __nv_bfloat16  g_curh[(size_t)M_ * HID_];
__device__ __nv_bfloat16  g_curl[(size_t)M_ * HID_];
__device__ __nv_bfloat16  g_Wqh [(size_t)3 * HID_ * HID_];   // W_qkv^T bf16 [3072,1024]
__device__ __nv_bfloat16  g_Wql [(size_t)3 * HID_ * HID_];
__device__ __nv_bfloat16  g_Woh [(size_t)HID_ * HID_];       // W_out^T hi
__device__ __nv_bfloat16  g_Wol [(size_t)HID_ * HID_];       // W_out^T lo
__device__ __nv_bfloat16  g_Qb  [(size_t)BH_ * S_ * HD_];    // expmapped q * inv_sqrt_d
__device__ __nv_bfloat16  g_Kb  [(size_t)BH_ * S_ * HD_];    // expmapped k
__device__ __nv_bfloat16  g_Vt  [(size_t)BH_ * HD_ * S_];    // V^T [z, d, s]
__device__ float          g_mp  [(size_t)M_ * H_ * MD_];     // per-head m partials [row][h][8]

// ==================================================================
// mma_core (R7-validated, used by gemm3 NT=3 path)
// ==================================================================
template<int NT, int STAGES>
__device__ __forceinline__ void mma_core(
    float (&acc)[4][4][4],
    const __nv_bfloat16* __restrict__ Ah, const __nv_bfloat16* __restrict__ Al,
    const __nv_bfloat16* __restrict__ Bh, const __nv_bfloat16* __restrict__ Bl,
    int ldA, int ldB, int K, char* smem)
{
    constexpr int TILE = 128 * 80;
    constexpr int NS   = (NT == 3) ? 4 : 2;
    constexpr int STG  = NS * TILE;
    const int tid  = threadIdx.x;
    const int lane = tid & 31, warp = tid >> 5;
    const int wm = (warp >> 2) * 64;
    const int wn = (warp & 3) * 32;
    const uint32_t sb = smem_u32(smem);

    auto issue = [&](int stage, int k0) {
        #pragma unroll
        for (int i = 0; i < 2; i++) {
            int q = tid + i * 256;
            int r = q >> 2, c = q & 3;
            uint32_t sa = sb + stage * STG + r * 80 + c * 16;
            CPA(sa,                              Ah + (size_t)r * ldA + k0 + c * 8);
            CPA(sa + (NT == 3 ? 2 : 1) * TILE,   Bh + (size_t)r * ldB + k0 + c * 8);
            if (NT == 3) {
                CPA(sa + TILE,                   Al + (size_t)r * ldA + k0 + c * 8);
                CPA(sa + 3 * TILE,               Bl + (size_t)r * ldB + k0 + c * 8);
            }
        }
        CP_COMMIT();
    };

    #pragma unroll
    for (int s = 0; s < STAGES - 1; s++) issue(s, s * 32);

    const int T = K / 32;
    for (int kt = 0; kt < T; kt++) {
        int rem;
        if (kt + STAGES - 1 < T) {
            issue((kt + STAGES - 1) % STAGES, (kt + STAGES - 1) * 32);
            rem = STAGES - 1;
        } else {
            rem = T - 1 - kt;
        }
        if (rem >= 2) CP_WAIT2(); else if (rem == 1) CP_WAIT1(); else CP_WAIT0();
        __syncthreads();
        const uint32_t ab = sb + (kt % STAGES) * STG;
        const uint32_t bb = ab + (NT == 3 ? 2 : 1) * TILE;
        #pragma unroll
        for (int kk = 0; kk < 2; kk++) {
            const uint32_t roff = (uint32_t)(lane & 15) * 80 + (2 * kk + (lane >> 4)) * 16;
            uint32_t bh[8], bl[8];
            LDSM4(bh,     bb + (uint32_t)wn * 80 + roff);
            LDSM4(bh + 4, bb + (uint32_t)(wn + 16) * 80 + roff);
            if (NT == 3) {
                LDSM4(bl,     bb + TILE + (uint32_t)wn * 80 + roff);
                LDSM4(bl + 4, bb + TILE + (uint32_t)(wn + 16) * 80 + roff);
            }
            #pragma unroll
            for (int mi = 0; mi < 4; mi++) {
                uint32_t ah[4], al[4];
                const uint32_t abase = ab + (uint32_t)(wm + mi * 16) * 80 + roff;
                LDSM4(ah, abase);
                if (NT == 3) LDSM4(al, abase + TILE);
                #pragma unroll
                for (int ni = 0; ni < 4; ni++) {
                    const int p = (ni >> 1) * 4, s = ni & 1;
                    uint32_t b0 = bh[p + s], b1 = bh[p + 2 + s];
                    MMA_B16(acc[mi][ni], ah[0], ah[1], ah[2], ah[3], b0, b1);
                    if (NT == 3) {
                        uint32_t d0 = bl[p + s], d1 = bl[p + 2 + s];
                        MMA_B16(acc[mi][ni], ah[0], ah[1], ah[2], ah[3], d0, d1);
                        MMA_B16(acc[mi][ni], al[0], al[1], al[2], al[3], b0, b1);
                    }
                }
            }
        }
        __syncthreads();
    }
}

#define ACC_ZERO4(acc) \
    _Pragma("unroll") for (int _i = 0; _i < 4; _i++) \
    _Pragma("unroll") for (int _j = 0; _j < 4; _j++) \
    _Pragma("unroll") for (int _k = 0; _k < 4; _k++) (acc)[_i][_j][_k] = 0.f;

// ==================================================================
// Fused QKV GEMM, CTA tile 256x128 (one head), warp tile 64x64.
// 8 warps = 4m x 2n. FLOP/byte 32 vs 21 -> smem-BW relief.
// part 0/1 (q/k): expmap0 epilogue -> bf16 [z,s,d]
// part 2 (v): transpose epilogue -> bf16 Vt [z,d,s]
// grid (24, 32), smem = 3*(256+128)*80 = 92160
// ==================================================================
__global__ __launch_bounds__(256, 1)
void gemm_qkv_kernel(const __nv_bfloat16* __restrict__ A,
                     const __nv_bfloat16* __restrict__ Bw,
                     const float* __restrict__ bias)
{
    extern __shared__ char smem[];
    const int bx = blockIdx.x;
    const int part = bx >> 3, h = bx & 7;
    const int brow = blockIdx.y * 256;
    const int b = brow >> 10, s0 = brow & 1023;
    const int z = b * H_ + h;

    const int tid = threadIdx.x;
    const int lane = tid & 31, warp = tid >> 5;
    const int wm = (warp >> 1) * 64;          // 0,64,128,192
    const int wn = (warp & 1) * 64;           // 0,64
    const uint32_t sb = smem_u32(smem);
    constexpr int ATILE = 256 * 80;           // 20480
    constexpr int STG   = ATILE + 128 * 80;   // 30720

    const __nv_bfloat16* Ag = A + (size_t)brow * HID_;
    const __nv_bfloat16* Bg = Bw + (size_t)(bx * 128) * HID_;

    auto issue = [&](int stage, int k0) {
        #pragma unroll
        for (int i = 0; i < 4; i++) {         // A: 1024 chunks
            int q = tid + i * 256;
            int r = q >> 2, c = q & 3;
            CPA(sb + stage * STG + r * 80 + c * 16, Ag + (size_t)r * HID_ + k0 + c * 8);
        }
        #pragma unroll
        for (int i = 0; i < 2; i++) {         // B: 512 chunks
            int q = tid + i * 256;
            int r = q >> 2, c = q & 3;
            CPA(sb + stage * STG + ATILE + r * 80 + c * 16, Bg + (size_t)r * HID_ + k0 + c * 8);
        }
        CP_COMMIT();
    };

    float acc[4][8][4];
    #pragma unroll
    for (int i = 0; i < 4; i++)
        #pragma unroll
        for (int j = 0; j < 8; j++)
            #pragma unroll
            for (int k = 0; k < 4; k++) acc[i][j][k] = 0.f;

    issue(0, 0); issue(1, 32);
    for (int kt = 0; kt < 32; kt++) {
        int rem;
        if (kt + 2 < 32) { issue((kt + 2) % 3, (kt + 2) * 32); rem = 2; }
        else rem = 31 - kt;
        if (rem >= 2) CP_WAIT2(); else if (rem == 1) CP_WAIT1(); else CP_WAIT0();
        __syncthreads();
        const uint32_t ab = sb + (kt % 3) * STG;
        const uint32_t bb = ab + ATILE;
        #pragma unroll
        for (int kk = 0; kk < 2; kk++) {
            const uint32_t roff = (uint32_t)(lane & 15) * 80 + (2 * kk + (lane >> 4)) * 16;
            uint32_t bh[16];
            #pragma unroll
            for (int nt = 0; nt < 4; nt++)
                LDSM4(bh + nt * 4, bb + (uint32_t)(wn + nt * 16) * 80 + roff);
            #pragma unroll
            for (int mi = 0; mi < 4; mi++) {
                uint32_t ah[4];
                LDSM4(ah, ab + (uint32_t)(wm + mi * 16) * 80 + roff);
                #pragma unroll
                for (int ni = 0; ni < 8; ni++) {
                    const int p = (ni >> 1) * 4, s = ni & 1;
                    MMA_B16(acc[mi][ni], ah[0], ah[1], ah[2], ah[3],
                            bh[p + s], bh[p + 2 + s]);
                }
            }
        }
        __syncthreads();
    }

    // add bias (column-only, same for both acc row halves)
    #pragma unroll
    for (int mi = 0; mi < 4; mi++)
        #pragma unroll
        for (int ni = 0; ni < 8; ni++) {
            int gc = bx * 128 + wn + ni * 8 + (lane & 3) * 2;
            acc[mi][ni][0] += bias[gc];     acc[mi][ni][1] += bias[gc + 1];
            acc[mi][ni][2] += bias[gc];     acc[mi][ni][3] += bias[gc + 1];
        }

    __nv_bfloat16* stb = (__nv_bfloat16*)smem;       // q/k: 256x136 ; v: 128x264
    float* red = (float*)(smem + 70656);             // [256][2]
    float* scs = (float*)(smem + 72704);             // [256]

    if (part < 2) {
        // per-row sum of squares over this warp's 64 cols -> quad reduce -> smem
        #pragma unroll
        for (int mi = 0; mi < 4; mi++) {
            int ra = wm + mi * 16 + (lane >> 2), rb = ra + 8;
            float ssa = 0.f, ssb = 0.f;
            #pragma unroll
            for (int ni = 0; ni < 8; ni++) {
                ssa += acc[mi][ni][0]*acc[mi][ni][0] + acc[mi][ni][1]*acc[mi][ni][1];
                ssb += acc[mi][ni][2]*acc[mi][ni][2] + acc[mi][ni][3]*acc[mi][ni][3];
            }
            ssa += __shfl_xor_sync(0xffffffffu, ssa, 1);
            ssa += __shfl_xor_sync(0xffffffffu, ssa, 2);
            ssb += __shfl_xor_sync(0xffffffffu, ssb, 1);
            ssb += __shfl_xor_sync(0xffffffffu, ssb, 2);
            if ((lane & 3) == 0) {
                red[ra * 2 + (warp & 1)] = ssa;
                red[rb * 2 + (warp & 1)] = ssb;
            }
        }
        __syncthreads();
        {
            float t = red[tid * 2] + red[tid * 2 + 1];   // tid 0..255 = row
            float n = fmaxf(sqrtf(t), EPS_);
            float sc = tanhf(n) / n;
            if (part == 0) sc *= INV_SQRT_D;
            scs[tid] = sc;
        }
        __syncthreads();
        #pragma unroll
        for (int mi = 0; mi < 4; mi++) {
            int ra = wm + mi * 16 + (lane >> 2), rb = ra + 8;
            float sa = scs[ra], sb2 = scs[rb];
            #pragma unroll
            for (int ni = 0; ni < 8; ni++) {
                int c = wn + ni * 8 + (lane & 3) * 2;
                *(__nv_bfloat162*)&stb[ra * 136 + c] =
                    __floats2bfloat162_rn(acc[mi][ni][0]*sa, acc[mi][ni][1]*sa);
                *(__nv_bfloat162*)&stb[rb * 136 + c] =
                    __floats2bfloat162_rn(acc[mi][ni][2]*sb2, acc[mi][ni][3]*sb2);
            }
        }
        __syncthreads();
        __nv_bfloat16* dst = (part ? g_Kb : g_Qb) + ((size_t)z * S_ + s0) * HD_;
        #pragma unroll
        for (int k = 0; k < 32; k++) {
            int ch = tid + k * 256;
            int outer = ch >> 5, in4 = (ch & 31) * 4;
            *(uint2*)(dst + (size_t)outer * HD_ + in4) = *(uint2*)&stb[outer * 136 + in4];
        }
    } else {
        // V: transposed staging [d=128][s=256], stride 264
        #pragma unroll
        for (int mi = 0; mi < 4; mi++) {
            int ra = wm + mi * 16 + (lane >> 2), rb = ra + 8;
            #pragma unroll
            for (int ni = 0; ni < 8; ni++) {
                int c = wn + ni * 8 + (lane & 3) * 2;
                stb[c * 264 + ra]       = __float2bfloat16(acc[mi][ni][0]);
                stb[(c + 1) * 264 + ra] = __float2bfloat16(acc[mi][ni][1]);
                stb[c * 264 + rb]       = __float2bfloat16(acc[mi][ni][2]);
                stb[(c + 1) * 264 + rb] = __float2bfloat16(acc[mi][ni][3]);
            }
        }
        __syncthreads();
        __nv_bfloat16* dst = g_Vt + (size_t)z * HD_ * S_ + s0;
        #pragma unroll
        for (int k = 0; k < 32; k++) {
            int ch = tid + k * 256;
            int outer = ch >> 6, in4 = (ch & 63) * 4;
            *(uint2*)(dst + (size_t)outer * S_ + in4) = *(uint2*)&stb[outer * 264 + in4];
        }
    }
}

// ==================================================================
// Flash attention, KB=64, 2 CTAs/SM, fused W_pinv epilogue (R11).
// grid (8, 64), 256 threads, smem = 106496 B.
// ==================================================================
#define STRQ 272
#define STRV 144
__global__ __launch_bounds__(256, 2)
void flash_kernel(const float* __restrict__ W_pinv)
{
    extern __shared__ char smem[];
    const int qb = blockIdx.x, z = blockIdx.y;
    const int b = z >> 3, h = z & 7;
    const int tid = threadIdx.x, lane = tid & 31, warp = tid >> 5;
    const uint32_t sb = smem_u32(smem);
    const uint32_t Qs = sb;
    const uint32_t Ks[2] = { sb + 34816u,  sb + 70656u };
    const uint32_t Vs[2] = { sb + 52224u,  sb + 88064u };

    const __nv_bfloat16* Qg = g_Qb + ((size_t)z * S_ + qb * 128) * HD_;
    const __nv_bfloat16* Kg = g_Kb + (size_t)z * S_ * HD_;
    const __nv_bfloat16* Vg = g_Vt + (size_t)z * HD_ * S_;

    auto issueKV = [&](int buf, int kb) {
        #pragma unroll
        for (int i = 0; i < 4; i++) {
            int ch = tid + i * 256;
            int r = ch >> 4, c = ch & 15;
            CPA(Ks[buf] + r * STRQ + c * 16, Kg + (size_t)(kb * 64 + r) * HD_ + c * 8);
        }
        #pragma unroll
        for (int i = 0; i < 4; i++) {
            int ch = tid + i * 256;
            int r = ch >> 3, c = ch & 7;
            CPA(Vs[buf] + r * STRV + c * 16, Vg + (size_t)r * S_ + kb * 64 + c * 8);
        }
        CP_COMMIT();
    };

    #pragma unroll
    for (int i = 0; i < 8; i++) {
        int ch = tid + i * 256;
        int r = ch >> 4, c = ch & 15;
        CPA(Qs + r * STRQ + c * 16, Qg + (size_t)r * HD_ + c * 8);
    }
    issueKV(0, 0);
    issueKV(1, 1);

    float acc_o[16][4];
    #pragma unroll
    for (int i = 0; i < 16; i++)
        #pragma unroll
        for (int j = 0; j < 4; j++) acc_o[i][j] = 0.f;
    float l0 = 0.f, l1 = 0.f;

    for (int kb = 0; kb < 16; kb++) {
        if (kb < 15) CP_WAIT1(); else CP_WAIT0();
        __syncthreads();
        const int buf = kb & 1;
        const uint32_t Kb = Ks[buf], Vb = Vs[buf];

        float acc_s[8][4];
        #pragma unroll
        for (int i = 0; i < 8; i++)
            #pragma unroll
            for (int j = 0; j < 4; j++) acc_s[i][j] = 0.f;

        #pragma unroll
        for (int ks = 0; ks < 8; ks++) {
            const uint32_t roff = (uint32_t)(lane & 15) * STRQ + (2 * ks + (lane >> 4)) * 16;
            uint32_t aq[4];
            LDSM4(aq, Qs + (uint32_t)(warp * 16) * STRQ + roff);
            #pragma unroll
            for (int nt = 0; nt < 4; nt++) {
                uint32_t bh[4];
                LDSM4(bh, Kb + (uint32_t)(nt * 16) * STRQ + roff);
                MMA_B16(acc_s[2 * nt],     aq[0], aq[1], aq[2], aq[3], bh[0], bh[2]);
                MMA_B16(acc_s[2 * nt + 1], aq[0], aq[1], aq[2], aq[3], bh[1], bh[3]);
            }
        }

        uint32_t Af[4][4];
        #pragma unroll
        for (int nt2 = 0; nt2 < 8; nt2++) {
            float e0 = __expf(acc_s[nt2][0]);
            float e1 = __expf(acc_s[nt2][1]);
            float e2 = __expf(acc_s[nt2][2]);
            float e3 = __expf(acc_s[nt2][3]);
            l0 += e0 + e1;
            l1 += e2 + e3;
            int kt = nt2 >> 1, hf = (nt2 & 1) * 2;
            Af[kt][hf]     = pack_bf2(e0, e1);
            Af[kt][hf + 1] = pack_bf2(e2, e3);
        }

        #pragma unroll
        for (int kt = 0; kt < 4; kt++) {
            const uint32_t roff = (uint32_t)(lane & 15) * STRV + (2 * kt + (lane >> 4)) * 16;
            #pragma unroll
            for (int nt = 0; nt < 8; nt++) {
                uint32_t bv[4];
                LDSM4(bv, Vb + (uint32_t)(nt * 16) * STRV + roff);
                MMA_B16(acc_o[2 * nt],     Af[kt][0], Af[kt][1], Af[kt][2], Af[kt][3], bv[0], bv[2]);
                MMA_B16(acc_o[2 * nt + 1], Af[kt][0], Af[kt][1], Af[kt][2], Af[kt][3], bv[1], bv[3]);
            }
        }
        __syncthreads();
        if (kb + 2 < 16) issueKV(buf, kb + 2);
    }

    l0 += __shfl_xor_sync(0xffffffffu, l0, 1);
    l0 += __shfl_xor_sync(0xffffffffu, l0, 2);
    l1 += __shfl_xor_sync(0xffffffffu, l1, 1);
    l1 += __shfl_xor_sync(0xffffffffu, l1, 2);
    const float i0 = 1.f / l0, i1 = 1.f / l1;

    __syncthreads();
    float* wp = (float*)smem;
    #pragma unroll
    for (int i = 0; i < 4; i++) {
        int idx = tid + i * 256;
        int c = idx >> 3, j = idx & 7;
        wp[c * 9 + j] = W_pinv[(size_t)(h * HD_ + c) * MD_ + j];
    }
    __syncthreads();

    float pm0[MD_], pm1[MD_];
    #pragma unroll
    for (int j = 0; j < MD_; j++) { pm0[j] = 0.f; pm1[j] = 0.f; }
    #pragma unroll
    for (int nt2 = 0; nt2 < 16; nt2++) {
        int c = nt2 * 8 + (lane & 3) * 2;
        float o0 = acc_o[nt2][0] * i0, o1 = acc_o[nt2][1] * i0;
        float o2 = acc_o[nt2][2] * i1, o3 = acc_o[nt2][3] * i1;
        #pragma unroll
        for (int j = 0; j < MD_; j++) {
            pm0[j] += o0 * wp[c * 9 + j] + o1 * wp[(c + 1) * 9 + j];
            pm1[j] += o2 * wp[c * 9 + j] + o3 * wp[(c + 1) * 9 + j];
        }
    }
    #pragma unroll
    for (int j = 0; j < MD_; j++) {
        pm0[j] += __shfl_xor_sync(0xffffffffu, pm0[j], 1);
        pm0[j] += __shfl_xor_sync(0xffffffffu, pm0[j], 2);
        pm1[j] += __shfl_xor_sync(0xffffffffu, pm1[j], 1);
        pm1[j] += __shfl_xor_sync(0xffffffffu, pm1[j], 2);
    }
    if ((lane & 3) == 0) {
        int s = qb * 128 + warp * 16 + (lane >> 2);
        float* d0 = g_mp + ((size_t)(b * S_ + s) * H_ + h) * MD_;
        float* d1 = g_mp + ((size_t)(b * S_ + s + 8) * H_ + h) * MD_;
        *(float4*)(d0)     = make_float4(pm0[0], pm0[1], pm0[2], pm0[3]);
        *(float4*)(d0 + 4) = make_float4(pm0[4], pm0[5], pm0[6], pm0[7]);
        *(float4*)(d1)     = make_float4(pm1[0], pm1[1], pm1[2], pm1[3]);
        *(float4*)(d1 + 4) = make_float4(pm1[4], pm1[5], pm1[6], pm1[7]);
    }
}

// ---- out-proj GEMM (hi/lo split): C = (Ah+Al)@(Bh+Bl)^T + bias ----
__global__ __launch_bounds__(256, 2)
void gemm3_kernel(const __nv_bfloat16* __restrict__ Ah, const __nv_bfloat16* __restrict__ Al,
                  const __nv_bfloat16* __restrict__ Bh, const __nv_bfloat16* __restrict__ Bl,
                  const float* __restrict__ bias, float* __restrict__ C, int N, int K)
{
    extern __shared__ char smem[];
    const int brow = blockIdx.y * 128, bcol = blockIdx.x * 128;
    float acc[4][4][4]; ACC_ZERO4(acc);
    mma_core<3, 2>(acc, Ah + (size_t)brow * K, Al + (size_t)brow * K,
                   Bh + (size_t)bcol * K, Bl + (size_t)bcol * K, K, K, K, smem);
    const int lane = threadIdx.x & 31, warp = threadIdx.x >> 5;
    const int wm = (warp >> 2) * 64, wn = (warp & 3) * 32;
    #pragma unroll
    for (int mi = 0; mi < 4; mi++)
        #pragma unroll
        for (int ni = 0; ni < 4; ni++) {
            int r = brow + wm + mi * 16 + (lane >> 2);
            int c = bcol + wn + ni * 8 + (lane & 3) * 2;
            float bx = bias[c], by = bias[c + 1];
            *(float2*)&C[(size_t)r * N + c]       = make_float2(acc[mi][ni][0] + bx, acc[mi][ni][1] + by);
            *(float2*)&C[(size_t)(r + 8) * N + c] = make_float2(acc[mi][ni][2] + bx, acc[mi][ni][3] + by);
        }
}

// ---------------- small kernels ----------------
__device__ __forceinline__ void split_store(float v, __nv_bfloat16* h, __nv_bfloat16* l, size_t i){
    __nv_bfloat16 hi = __float2bfloat16(v);
    h[i] = hi;
    l[i] = __float2bfloat16(v - __bfloat162float(hi));
}

__global__ void copy_x_kernel(const float* __restrict__ x){
    size_t i = (size_t)blockIdx.x * blockDim.x + threadIdx.x;
    float4 v = ((const float4*)x)[i];
    ((float4*)g_cur)[i] = v;
    size_t e = i * 4;
    split_store(v.x, g_curh, g_curl, e + 0);
    split_store(v.y, g_curh, g_curl, e + 1);
    split_store(v.z, g_curh, g_curl, e + 2);
    split_store(v.w, g_curh, g_curl, e + 3);
}

__global__ void wt_kernel(const float* __restrict__ src,
                          __nv_bfloat16* __restrict__ dh, __nv_bfloat16* __restrict__ dl,
                          int K, int N)
{
    __shared__ float t[32][33];
    const int n0 = blockIdx.x * 32, k0 = blockIdx.y * 32;
    const int tx = threadIdx.x, ty = threadIdx.y;
    for (int i = ty; i < 32; i += 8)
        t[i][tx] = src[(size_t)(k0 + i) * N + n0 + tx];
    __syncthreads();
    for (int i = ty; i < 32; i += 8)
        split_store(t[tx][i], dh, dl, (size_t)(n0 + i) * K + k0 + tx);
}

// cur += (sum_h mp[row][h] + b_pinv) @ Wa + ba ; refresh hi/lo
__global__ void update_kernel(const float* __restrict__ b_pinv,
                              const float* __restrict__ Wa, const float* __restrict__ ba)
{
    const int row = blockIdx.x, tid = threadIdx.x;
    __shared__ float m[MD_];
    if (tid < MD_) {
        const float* mp = g_mp + (size_t)row * H_ * MD_;
        float s = b_pinv[tid];
        #pragma unroll
        for (int hh = 0; hh < H_; hh++) s += mp[hh * MD_ + tid];
        m[tid] = s;
    }
    __syncthreads();
    float mv[MD_];
    #pragma unroll
    for (int j = 0; j < MD_; j++) mv[j] = m[j];
    #pragma unroll
    for (int t = 0; t < HID_ / 256; t++) {
        int col = tid + t * 256;
        float u = ba[col];
        #pragma unroll
        for (int j = 0; j < MD_; j++) u += mv[j] * Wa[j * HID_ + col];
        size_t idx = (size_t)row * HID_ + col;
        float nc = g_cur[idx] + u;
        g_cur[idx] = nc;
        split_store(nc, g_curh, g_curl, idx);
    }
}

// ---------------- launcher ----------------
extern "C" void kernel_launch(void* const* d_in, const int* in_sizes, int n_in,
                              void* d_out, int out_size)
{
    const float* x      = (const float*)d_in[0];
    const float* W_qkv  = (const float*)d_in[1];
    const float* b_qkv  = (const float*)d_in[2];
    const float* W_pinv = (const float*)d_in[3];
    const float* b_pinv = (const float*)d_in[4];
    const float* W_attn = (const float*)d_in[5];
    const float* b_attn = (const float*)d_in[6];
    const float* W_out  = (const float*)d_in[7];
    const float* b_out  = (const float*)d_in[8];
    float* out = (float*)d_out;

    const int SM1 = 3 * (256 + 128) * 80;   // 92160 (gemm_qkv, 3-stage 256x128)
    const int SM3 = 2 * 4 * 128 * 80;       // 81920 (gemm3, 2-stage)
    const int SMF = 106496;                 // flash (2 CTAs/SM)
    cudaFuncSetAttribute(gemm_qkv_kernel, cudaFuncAttributeMaxDynamicSharedMemorySize, SM1);
    cudaFuncSetAttribute(gemm3_kernel,    cudaFuncAttributeMaxDynamicSharedMemorySize, SM3);
    cudaFuncSetAttribute(flash_kernel,    cudaFuncAttributeMaxDynamicSharedMemorySize, SMF);

    __nv_bfloat16 *curh = nullptr, *curl = nullptr, *wqh = nullptr, *wql = nullptr,
                  *woh = nullptr, *wol = nullptr;
    cudaGetSymbolAddress((void**)&curh, g_curh);
    cudaGetSymbolAddress((void**)&curl, g_curl);
    cudaGetSymbolAddress((void**)&wqh,  g_Wqh);
    cudaGetSymbolAddress((void**)&wql,  g_Wql);
    cudaGetSymbolAddress((void**)&woh,  g_Woh);
    cudaGetSymbolAddress((void**)&wol,  g_Wol);

    copy_x_kernel<<<(M_ * HID_) / 4 / 256, 256>>>(x);
    wt_kernel<<<dim3(3 * HID_ / 32, HID_ / 32), dim3(32, 8)>>>(W_qkv, wqh, wql, HID_, 3 * HID_);
    wt_kernel<<<dim3(HID_ / 32, HID_ / 32), dim3(32, 8)>>>(W_out, woh, wol, HID_, HID_);

    for (int l = 0; l < L_; ++l) {
        gemm_qkv_kernel<<<dim3(24, 32), 256, SM1>>>(curh, wqh, b_qkv);
        flash_kernel<<<dim3(8, BH_), 256, SMF>>>(W_pinv);
        update_kernel<<<M_, 256>>>(b_pinv,
                                   W_attn + (size_t)l * MD_ * HID_,
                                   b_attn + (size_t)l * HID_);
    }

    gemm3_kernel<<<dim3(HID_ / 128, M_ / 128), 256, SM3>>>(
        curh, curl, woh, wol, b_out, out, HID_, HID_);
}

// round 16
// speedup vs baseline: 1.0498x; 1.0498x over previous
#include <cuda_runtime.h>
#include <cuda_bf16.h>
#include <cstdint>
#include <math.h>

#define B_    8
#define S_    1024
#define HID_  1024
#define H_    8
#define HD_   128
#define MD_   8
#define L_    3
#define M_    (B_*S_)
#define BH_   (B_*H_)
#define EPS_  1e-7f
#define INV_SQRT_D 0.08838834764831845f

// ---------------- PTX helpers (plain sm_80+ features only) ----------------
__device__ __forceinline__ uint32_t smem_u32(const void* p){
    uint32_t a;
    asm("{ .reg .u64 t; cvta.to.shared.u64 t, %1; cvt.u32.u64 %0, t; }" : "=r"(a) : "l"(p));
    return a;
}
#define CPA(sa, gp) \
    asm volatile("cp.async.cg.shared.global [%0], [%1], 16;" \
        :: "r"(sa), "l"(__cvta_generic_to_global((const void*)(gp))) : "memory")
#define CP_COMMIT() asm volatile("cp.async.commit_group;" ::: "memory")
#define CP_WAIT2()  asm volatile("cp.async.wait_group 2;" ::: "memory")
#define CP_WAIT1()  asm volatile("cp.async.wait_group 1;" ::: "memory")
#define CP_WAIT0()  asm volatile("cp.async.wait_group 0;" ::: "memory")

#define LDSM4(r, addr) \
    asm volatile("ldmatrix.sync.aligned.m8n8.x4.shared.b16 {%0,%1,%2,%3}, [%4];" \
        : "=r"((r)[0]), "=r"((r)[1]), "=r"((r)[2]), "=r"((r)[3]) : "r"(addr))

#define MMA_B16(c, a0,a1,a2,a3, b0,b1) \
    asm volatile("mma.sync.aligned.m16n8k16.row.col.f32.bf16.bf16.f32 " \
        "{%0,%1,%2,%3}, {%4,%5,%6,%7}, {%8,%9}, {%0,%1,%2,%3};" \
        : "+f"((c)[0]), "+f"((c)[1]), "+f"((c)[2]), "+f"((c)[3]) \
        : "r"(a0), "r"(a1), "r"(a2), "r"(a3), "r"(b0), "r"(b1))

__device__ __forceinline__ uint32_t pack_bf2(float a, float b){
    __nv_bfloat162 t = __floats2bfloat162_rn(a, b);
    return *(uint32_t*)&t;
}

// ---------------- scratch ----------------
__device__ float          g_cur [(size_t)M_ * HID_];
__device__ __nv_bfloat16  g_curh[(size_t)M_ * HID_];
__device__ __nv_bfloat16  g_curl[(size_t)M_ * HID_];
__device__ __nv_bfloat16  g_Wqh [(size_t)3 * HID_ * HID_];   // W_qkv^T bf16 [3072,1024]
__device__ __nv_bfloat16  g_Wql [(size_t)3 * HID_ * HID_];
__device__ __nv_bfloat16  g_Woh [(size_t)HID_ * HID_];       // W_out^T hi
__device__ __nv_bfloat16  g_Wol [(size_t)HID_ * HID_];       // W_out^T lo
__device__ __nv_bfloat16  g_Qb  [(size_t)BH_ * S_ * HD_];    // expmapped q * inv_sqrt_d
__device__ __nv_bfloat16  g_Kb  [(size_t)BH_ * S_ * HD_];    // expmapped k
__device__ __nv_bfloat16  g_Vt  [(size_t)BH_ * HD_ * S_];    // V^T [z, d, s]
__device__ float          g_mp  [(size_t)M_ * H_ * MD_];     // per-head m partials [row][h][8]

// ==================================================================
// mma_core (R7-validated; used by gemm3 NT=3 path, 256 threads)
// ==================================================================
template<int NT, int STAGES>
__device__ __forceinline__ void mma_core(
    float (&acc)[4][4][4],
    const __nv_bfloat16* __restrict__ Ah, const __nv_bfloat16* __restrict__ Al,
    const __nv_bfloat16* __restrict__ Bh, const __nv_bfloat16* __restrict__ Bl,
    int ldA, int ldB, int K, char* smem)
{
    constexpr int TILE = 128 * 80;
    constexpr int NS   = (NT == 3) ? 4 : 2;
    constexpr int STG  = NS * TILE;
    const int tid  = threadIdx.x;
    const int lane = tid & 31, warp = tid >> 5;
    const int wm = (warp >> 2) * 64;
    const int wn = (warp & 3) * 32;
    const uint32_t sb = smem_u32(smem);

    auto issue = [&](int stage, int k0) {
        #pragma unroll
        for (int i = 0; i < 2; i++) {
            int q = tid + i * 256;
            int r = q >> 2, c = q & 3;
            uint32_t sa = sb + stage * STG + r * 80 + c * 16;
            CPA(sa,                              Ah + (size_t)r * ldA + k0 + c * 8);
            CPA(sa + (NT == 3 ? 2 : 1) * TILE,   Bh + (size_t)r * ldB + k0 + c * 8);
            if (NT == 3) {
                CPA(sa + TILE,                   Al + (size_t)r * ldA + k0 + c * 8);
                CPA(sa + 3 * TILE,               Bl + (size_t)r * ldB + k0 + c * 8);
            }
        }
        CP_COMMIT();
    };

    #pragma unroll
    for (int s = 0; s < STAGES - 1; s++) issue(s, s * 32);

    const int T = K / 32;
    for (int kt = 0; kt < T; kt++) {
        int rem;
        if (kt + STAGES - 1 < T) {
            issue((kt + STAGES - 1) % STAGES, (kt + STAGES - 1) * 32);
            rem = STAGES - 1;
        } else {
            rem = T - 1 - kt;
        }
        if (rem >= 2) CP_WAIT2(); else if (rem == 1) CP_WAIT1(); else CP_WAIT0();
        __syncthreads();
        const uint32_t ab = sb + (kt % STAGES) * STG;
        const uint32_t bb = ab + (NT == 3 ? 2 : 1) * TILE;
        #pragma unroll
        for (int kk = 0; kk < 2; kk++) {
            const uint32_t roff = (uint32_t)(lane & 15) * 80 + (2 * kk + (lane >> 4)) * 16;
            uint32_t bh[8], bl[8];
            LDSM4(bh,     bb + (uint32_t)wn * 80 + roff);
            LDSM4(bh + 4, bb + (uint32_t)(wn + 16) * 80 + roff);
            if (NT == 3) {
                LDSM4(bl,     bb + TILE + (uint32_t)wn * 80 + roff);
                LDSM4(bl + 4, bb + TILE + (uint32_t)(wn + 16) * 80 + roff);
            }
            #pragma unroll
            for (int mi = 0; mi < 4; mi++) {
                uint32_t ah[4], al[4];
                const uint32_t abase = ab + (uint32_t)(wm + mi * 16) * 80 + roff;
                LDSM4(ah, abase);
                if (NT == 3) LDSM4(al, abase + TILE);
                #pragma unroll
                for (int ni = 0; ni < 4; ni++) {
                    const int p = (ni >> 1) * 4, s = ni & 1;
                    uint32_t b0 = bh[p + s], b1 = bh[p + 2 + s];
                    MMA_B16(acc[mi][ni], ah[0], ah[1], ah[2], ah[3], b0, b1);
                    if (NT == 3) {
                        uint32_t d0 = bl[p + s], d1 = bl[p + 2 + s];
                        MMA_B16(acc[mi][ni], ah[0], ah[1], ah[2], ah[3], d0, d1);
                        MMA_B16(acc[mi][ni], al[0], al[1], al[2], al[3], b0, b1);
                    }
                }
            }
        }
        __syncthreads();
    }
}

#define ACC_ZERO4(acc) \
    _Pragma("unroll") for (int _i = 0; _i < 4; _i++) \
    _Pragma("unroll") for (int _j = 0; _j < 4; _j++) \
    _Pragma("unroll") for (int _k = 0; _k < 4; _k++) (acc)[_i][_j][_k] = 0.f;

// ==================================================================
// Fused QKV GEMM: CTA tile 128x128 (one head), 128 threads,
// 4 warps = 2m x 2n of 64x64 warp tiles (FLOP/byte 32), 2 CTAs/SM.
// part 0/1 (q/k): expmap0 epilogue -> bf16 [z,s,d]
// part 2 (v): transpose epilogue -> bf16 Vt [z,d,s]
// grid (24, 64), smem = 3*2*10240 = 61440
// ==================================================================
__global__ __launch_bounds__(128, 2)
void gemm_qkv_kernel(const __nv_bfloat16* __restrict__ A,
                     const __nv_bfloat16* __restrict__ Bw,
                     const float* __restrict__ bias)
{
    extern __shared__ char smem[];
    const int bx = blockIdx.x;
    const int part = bx >> 3, h = bx & 7;
    const int brow = blockIdx.y * 128;
    const int b = blockIdx.y >> 3, s0 = (blockIdx.y & 7) * 128;
    const int z = b * H_ + h;

    const int tid = threadIdx.x;
    const int lane = tid & 31, warp = tid >> 5;
    const int wm = (warp >> 1) * 64;          // 0, 64
    const int wn = (warp & 1) * 64;           // 0, 64
    const uint32_t sb = smem_u32(smem);
    constexpr int TILE = 128 * 80;            // 10240
    constexpr int STG  = 2 * TILE;            // 20480

    const __nv_bfloat16* Ag = A  + (size_t)brow * HID_;
    const __nv_bfloat16* Bg = Bw + (size_t)(bx * 128) * HID_;

    auto issue = [&](int stage, int k0) {
        #pragma unroll
        for (int i = 0; i < 4; i++) {         // A: 512 chunks / 128 thr
            int q = tid + i * 128;
            int r = q >> 2, c = q & 3;
            CPA(sb + stage * STG + r * 80 + c * 16, Ag + (size_t)r * HID_ + k0 + c * 8);
        }
        #pragma unroll
        for (int i = 0; i < 4; i++) {         // B: 512 chunks
            int q = tid + i * 128;
            int r = q >> 2, c = q & 3;
            CPA(sb + stage * STG + TILE + r * 80 + c * 16, Bg + (size_t)r * HID_ + k0 + c * 8);
        }
        CP_COMMIT();
    };

    float acc[4][8][4];
    #pragma unroll
    for (int i = 0; i < 4; i++)
        #pragma unroll
        for (int j = 0; j < 8; j++)
            #pragma unroll
            for (int k = 0; k < 4; k++) acc[i][j][k] = 0.f;

    issue(0, 0); issue(1, 32);
    for (int kt = 0; kt < 32; kt++) {
        int rem;
        if (kt + 2 < 32) { issue((kt + 2) % 3, (kt + 2) * 32); rem = 2; }
        else rem = 31 - kt;
        if (rem >= 2) CP_WAIT2(); else if (rem == 1) CP_WAIT1(); else CP_WAIT0();
        __syncthreads();
        const uint32_t ab = sb + (kt % 3) * STG;
        const uint32_t bb = ab + TILE;
        #pragma unroll
        for (int kk = 0; kk < 2; kk++) {
            const uint32_t roff = (uint32_t)(lane & 15) * 80 + (2 * kk + (lane >> 4)) * 16;
            uint32_t bh[16];
            #pragma unroll
            for (int nt = 0; nt < 4; nt++)
                LDSM4(bh + nt * 4, bb + (uint32_t)(wn + nt * 16) * 80 + roff);
            #pragma unroll
            for (int mi = 0; mi < 4; mi++) {
                uint32_t ah[4];
                LDSM4(ah, ab + (uint32_t)(wm + mi * 16) * 80 + roff);
                #pragma unroll
                for (int ni = 0; ni < 8; ni++) {
                    const int p = (ni >> 1) * 4, s = ni & 1;
                    MMA_B16(acc[mi][ni], ah[0], ah[1], ah[2], ah[3],
                            bh[p + s], bh[p + 2 + s]);
                }
            }
        }
        __syncthreads();
    }

    // add bias
    #pragma unroll
    for (int mi = 0; mi < 4; mi++)
        #pragma unroll
        for (int ni = 0; ni < 8; ni++) {
            int gc = bx * 128 + wn + ni * 8 + (lane & 3) * 2;
            acc[mi][ni][0] += bias[gc];     acc[mi][ni][1] += bias[gc + 1];
            acc[mi][ni][2] += bias[gc];     acc[mi][ni][3] += bias[gc + 1];
        }

    __nv_bfloat16* stb = (__nv_bfloat16*)smem;       // 128 x 136 bf16 staging (34816 B)
    float* red = (float*)(smem + 34816);             // [128][2]
    float* scs = (float*)(smem + 35840);             // [128]

    if (part < 2) {
        // per-row sum of squares over this warp's 64 cols -> quad reduce -> smem
        #pragma unroll
        for (int mi = 0; mi < 4; mi++) {
            int ra = wm + mi * 16 + (lane >> 2), rb = ra + 8;
            float ssa = 0.f, ssb = 0.f;
            #pragma unroll
            for (int ni = 0; ni < 8; ni++) {
                ssa += acc[mi][ni][0]*acc[mi][ni][0] + acc[mi][ni][1]*acc[mi][ni][1];
                ssb += acc[mi][ni][2]*acc[mi][ni][2] + acc[mi][ni][3]*acc[mi][ni][3];
            }
            ssa += __shfl_xor_sync(0xffffffffu, ssa, 1);
            ssa += __shfl_xor_sync(0xffffffffu, ssa, 2);
            ssb += __shfl_xor_sync(0xffffffffu, ssb, 1);
            ssb += __shfl_xor_sync(0xffffffffu, ssb, 2);
            if ((lane & 3) == 0) {
                red[ra * 2 + (warp & 1)] = ssa;
                red[rb * 2 + (warp & 1)] = ssb;
            }
        }
        __syncthreads();
        {
            float t = red[tid * 2] + red[tid * 2 + 1];   // tid = row (block is 128 thr)
            float n = fmaxf(sqrtf(t), EPS_);
            float sc = tanhf(n) / n;
            if (part == 0) sc *= INV_SQRT_D;
            scs[tid] = sc;
        }
        __syncthreads();
        #pragma unroll
        for (int mi = 0; mi < 4; mi++) {
            int ra = wm + mi * 16 + (lane >> 2), rb = ra + 8;
            float sa = scs[ra], sb2 = scs[rb];
            #pragma unroll
            for (int ni = 0; ni < 8; ni++) {
                int c = wn + ni * 8 + (lane & 3) * 2;
                *(__nv_bfloat162*)&stb[ra * 136 + c] =
                    __floats2bfloat162_rn(acc[mi][ni][0]*sa, acc[mi][ni][1]*sa);
                *(__nv_bfloat162*)&stb[rb * 136 + c] =
                    __floats2bfloat162_rn(acc[mi][ni][2]*sb2, acc[mi][ni][3]*sb2);
            }
        }
        __syncthreads();
        __nv_bfloat16* dst = (part ? g_Kb : g_Qb) + ((size_t)z * S_ + s0) * HD_;
        #pragma unroll
        for (int k = 0; k < 32; k++) {
            int ch = tid + k * 128;                 // 4096 uint2 chunks
            int outer = ch >> 5, in4 = (ch & 31) * 4;
            *(uint2*)(dst + (size_t)outer * HD_ + in4) = *(uint2*)&stb[outer * 136 + in4];
        }
    } else {
        // V: transposed staging [d=128][s=128], stride 136
        #pragma unroll
        for (int mi = 0; mi < 4; mi++) {
            int ra = wm + mi * 16 + (lane >> 2), rb = ra + 8;
            #pragma unroll
            for (int ni = 0; ni < 8; ni++) {
                int c = wn + ni * 8 + (lane & 3) * 2;
                stb[c * 136 + ra]       = __float2bfloat16(acc[mi][ni][0]);
                stb[(c + 1) * 136 + ra] = __float2bfloat16(acc[mi][ni][1]);
                stb[c * 136 + rb]       = __float2bfloat16(acc[mi][ni][2]);
                stb[(c + 1) * 136 + rb] = __float2bfloat16(acc[mi][ni][3]);
            }
        }
        __syncthreads();
        __nv_bfloat16* dst = g_Vt + (size_t)z * HD_ * S_ + s0;
        #pragma unroll
        for (int k = 0; k < 32; k++) {
            int ch = tid + k * 128;
            int outer = ch >> 5, in4 = (ch & 31) * 4;
            *(uint2*)(dst + (size_t)outer * S_ + in4) = *(uint2*)&stb[outer * 136 + in4];
        }
    }
}

// ==================================================================
// Flash attention, KB=64, 2 CTAs/SM, fused W_pinv epilogue (R11).
// grid (8, 64), 256 threads, smem = 106496 B.
// ==================================================================
#define STRQ 272
#define STRV 144
__global__ __launch_bounds__(256, 2)
void flash_kernel(const float* __restrict__ W_pinv)
{
    extern __shared__ char smem[];
    const int qb = blockIdx.x, z = blockIdx.y;
    const int b = z >> 3, h = z & 7;
    const int tid = threadIdx.x, lane = tid & 31, warp = tid >> 5;
    const uint32_t sb = smem_u32(smem);
    const uint32_t Qs = sb;
    const uint32_t Ks[2] = { sb + 34816u,  sb + 70656u };
    const uint32_t Vs[2] = { sb + 52224u,  sb + 88064u };

    const __nv_bfloat16* Qg = g_Qb + ((size_t)z * S_ + qb * 128) * HD_;
    const __nv_bfloat16* Kg = g_Kb + (size_t)z * S_ * HD_;
    const __nv_bfloat16* Vg = g_Vt + (size_t)z * HD_ * S_;

    auto issueKV = [&](int buf, int kb) {
        #pragma unroll
        for (int i = 0; i < 4; i++) {
            int ch = tid + i * 256;
            int r = ch >> 4, c = ch & 15;
            CPA(Ks[buf] + r * STRQ + c * 16, Kg + (size_t)(kb * 64 + r) * HD_ + c * 8);
        }
        #pragma unroll
        for (int i = 0; i < 4; i++) {
            int ch = tid + i * 256;
            int r = ch >> 3, c = ch & 7;
            CPA(Vs[buf] + r * STRV + c * 16, Vg + (size_t)r * S_ + kb * 64 + c * 8);
        }
        CP_COMMIT();
    };

    #pragma unroll
    for (int i = 0; i < 8; i++) {
        int ch = tid + i * 256;
        int r = ch >> 4, c = ch & 15;
        CPA(Qs + r * STRQ + c * 16, Qg + (size_t)r * HD_ + c * 8);
    }
    issueKV(0, 0);
    issueKV(1, 1);

    float acc_o[16][4];
    #pragma unroll
    for (int i = 0; i < 16; i++)
        #pragma unroll
        for (int j = 0; j < 4; j++) acc_o[i][j] = 0.f;
    float l0 = 0.f, l1 = 0.f;

    for (int kb = 0; kb < 16; kb++) {
        if (kb < 15) CP_WAIT1(); else CP_WAIT0();
        __syncthreads();
        const int buf = kb & 1;
        const uint32_t Kb = Ks[buf], Vb = Vs[buf];

        float acc_s[8][4];
        #pragma unroll
        for (int i = 0; i < 8; i++)
            #pragma unroll
            for (int j = 0; j < 4; j++) acc_s[i][j] = 0.f;

        #pragma unroll
        for (int ks = 0; ks < 8; ks++) {
            const uint32_t roff = (uint32_t)(lane & 15) * STRQ + (2 * ks + (lane >> 4)) * 16;
            uint32_t aq[4];
            LDSM4(aq, Qs + (uint32_t)(warp * 16) * STRQ + roff);
            #pragma unroll
            for (int nt = 0; nt < 4; nt++) {
                uint32_t bh[4];
                LDSM4(bh, Kb + (uint32_t)(nt * 16) * STRQ + roff);
                MMA_B16(acc_s[2 * nt],     aq[0], aq[1], aq[2], aq[3], bh[0], bh[2]);
                MMA_B16(acc_s[2 * nt + 1], aq[0], aq[1], aq[2], aq[3], bh[1], bh[3]);
            }
        }

        uint32_t Af[4][4];
        #pragma unroll
        for (int nt2 = 0; nt2 < 8; nt2++) {
            float e0 = __expf(acc_s[nt2][0]);
            float e1 = __expf(acc_s[nt2][1]);
            float e2 = __expf(acc_s[nt2][2]);
            float e3 = __expf(acc_s[nt2][3]);
            l0 += e0 + e1;
            l1 += e2 + e3;
            int kt = nt2 >> 1, hf = (nt2 & 1) * 2;
            Af[kt][hf]     = pack_bf2(e0, e1);
            Af[kt][hf + 1] = pack_bf2(e2, e3);
        }

        #pragma unroll
        for (int kt = 0; kt < 4; kt++) {
            const uint32_t roff = (uint32_t)(lane & 15) * STRV + (2 * kt + (lane >> 4)) * 16;
            #pragma unroll
            for (int nt = 0; nt < 8; nt++) {
                uint32_t bv[4];
                LDSM4(bv, Vb + (uint32_t)(nt * 16) * STRV + roff);
                MMA_B16(acc_o[2 * nt],     Af[kt][0], Af[kt][1], Af[kt][2], Af[kt][3], bv[0], bv[2]);
                MMA_B16(acc_o[2 * nt + 1], Af[kt][0], Af[kt][1], Af[kt][2], Af[kt][3], bv[1], bv[3]);
            }
        }
        __syncthreads();
        if (kb + 2 < 16) issueKV(buf, kb + 2);
    }

    l0 += __shfl_xor_sync(0xffffffffu, l0, 1);
    l0 += __shfl_xor_sync(0xffffffffu, l0, 2);
    l1 += __shfl_xor_sync(0xffffffffu, l1, 1);
    l1 += __shfl_xor_sync(0xffffffffu, l1, 2);
    const float i0 = 1.f / l0, i1 = 1.f / l1;

    __syncthreads();
    float* wp = (float*)smem;
    #pragma unroll
    for (int i = 0; i < 4; i++) {
        int idx = tid + i * 256;
        int c = idx >> 3, j = idx & 7;
        wp[c * 9 + j] = W_pinv[(size_t)(h * HD_ + c) * MD_ + j];
    }
    __syncthreads();

    float pm0[MD_], pm1[MD_];
    #pragma unroll
    for (int j = 0; j < MD_; j++) { pm0[j] = 0.f; pm1[j] = 0.f; }
    #pragma unroll
    for (int nt2 = 0; nt2 < 16; nt2++) {
        int c = nt2 * 8 + (lane & 3) * 2;
        float o0 = acc_o[nt2][0] * i0, o1 = acc_o[nt2][1] * i0;
        float o2 = acc_o[nt2][2] * i1, o3 = acc_o[nt2][3] * i1;
        #pragma unroll
        for (int j = 0; j < MD_; j++) {
            pm0[j] += o0 * wp[c * 9 + j] + o1 * wp[(c + 1) * 9 + j];
            pm1[j] += o2 * wp[c * 9 + j] + o3 * wp[(c + 1) * 9 + j];
        }
    }
    #pragma unroll
    for (int j = 0; j < MD_; j++) {
        pm0[j] += __shfl_xor_sync(0xffffffffu, pm0[j], 1);
        pm0[j] += __shfl_xor_sync(0xffffffffu, pm0[j], 2);
        pm1[j] += __shfl_xor_sync(0xffffffffu, pm1[j], 1);
        pm1[j] += __shfl_xor_sync(0xffffffffu, pm1[j], 2);
    }
    if ((lane & 3) == 0) {
        int s = qb * 128 + warp * 16 + (lane >> 2);
        float* d0 = g_mp + ((size_t)(b * S_ + s) * H_ + h) * MD_;
        float* d1 = g_mp + ((size_t)(b * S_ + s + 8) * H_ + h) * MD_;
        *(float4*)(d0)     = make_float4(pm0[0], pm0[1], pm0[2], pm0[3]);
        *(float4*)(d0 + 4) = make_float4(pm0[4], pm0[5], pm0[6], pm0[7]);
        *(float4*)(d1)     = make_float4(pm1[0], pm1[1], pm1[2], pm1[3]);
        *(float4*)(d1 + 4) = make_float4(pm1[4], pm1[5], pm1[6], pm1[7]);
    }
}

// ---- out-proj GEMM (hi/lo split): C = (Ah+Al)@(Bh+Bl)^T + bias ----
__global__ __launch_bounds__(256, 2)
void gemm3_kernel(const __nv_bfloat16* __restrict__ Ah, const __nv_bfloat16* __restrict__ Al,
                  const __nv_bfloat16* __restrict__ Bh, const __nv_bfloat16* __restrict__ Bl,
                  const float* __restrict__ bias, float* __restrict__ C, int N, int K)
{
    extern __shared__ char smem[];
    const int brow = blockIdx.y * 128, bcol = blockIdx.x * 128;
    float acc[4][4][4]; ACC_ZERO4(acc);
    mma_core<3, 2>(acc, Ah + (size_t)brow * K, Al + (size_t)brow * K,
                   Bh + (size_t)bcol * K, Bl + (size_t)bcol * K, K, K, K, smem);
    const int lane = threadIdx.x & 31, warp = threadIdx.x >> 5;
    const int wm = (warp >> 2) * 64, wn = (warp & 3) * 32;
    #pragma unroll
    for (int mi = 0; mi < 4; mi++)
        #pragma unroll
        for (int ni = 0; ni < 4; ni++) {
            int r = brow + wm + mi * 16 + (lane >> 2);
            int c = bcol + wn + ni * 8 + (lane & 3) * 2;
            float bx = bias[c], by = bias[c + 1];
            *(float2*)&C[(size_t)r * N + c]       = make_float2(acc[mi][ni][0] + bx, acc[mi][ni][1] + by);
            *(float2*)&C[(size_t)(r + 8) * N + c] = make_float2(acc[mi][ni][2] + bx, acc[mi][ni][3] + by);
        }
}

// ---------------- small kernels ----------------
__device__ __forceinline__ void split_store(float v, __nv_bfloat16* h, __nv_bfloat16* l, size_t i){
    __nv_bfloat16 hi = __float2bfloat16(v);
    h[i] = hi;
    l[i] = __float2bfloat16(v - __bfloat162float(hi));
}

__global__ void copy_x_kernel(const float* __restrict__ x){
    size_t i = (size_t)blockIdx.x * blockDim.x + threadIdx.x;
    float4 v = ((const float4*)x)[i];
    ((float4*)g_cur)[i] = v;
    size_t e = i * 4;
    split_store(v.x, g_curh, g_curl, e + 0);
    split_store(v.y, g_curh, g_curl, e + 1);
    split_store(v.z, g_curh, g_curl, e + 2);
    split_store(v.w, g_curh, g_curl, e + 3);
}

__global__ void wt_kernel(const float* __restrict__ src,
                          __nv_bfloat16* __restrict__ dh, __nv_bfloat16* __restrict__ dl,
                          int K, int N)
{
    __shared__ float t[32][33];
    const int n0 = blockIdx.x * 32, k0 = blockIdx.y * 32;
    const int tx = threadIdx.x, ty = threadIdx.y;
    for (int i = ty; i < 32; i += 8)
        t[i][tx] = src[(size_t)(k0 + i) * N + n0 + tx];
    __syncthreads();
    for (int i = ty; i < 32; i += 8)
        split_store(t[tx][i], dh, dl, (size_t)(n0 + i) * K + k0 + tx);
}

// cur += (sum_h mp[row][h] + b_pinv) @ Wa + ba ; refresh hi/lo
__global__ void update_kernel(const float* __restrict__ b_pinv,
                              const float* __restrict__ Wa, const float* __restrict__ ba)
{
    const int row = blockIdx.x, tid = threadIdx.x;
    __shared__ float m[MD_];
    if (tid < MD_) {
        const float* mp = g_mp + (size_t)row * H_ * MD_;
        float s = b_pinv[tid];
        #pragma unroll
        for (int hh = 0; hh < H_; hh++) s += mp[hh * MD_ + tid];
        m[tid] = s;
    }
    __syncthreads();
    float mv[MD_];
    #pragma unroll
    for (int j = 0; j < MD_; j++) mv[j] = m[j];
    #pragma unroll
    for (int t = 0; t < HID_ / 256; t++) {
        int col = tid + t * 256;
        float u = ba[col];
        #pragma unroll
        for (int j = 0; j < MD_; j++) u += mv[j] * Wa[j * HID_ + col];
        size_t idx = (size_t)row * HID_ + col;
        float nc = g_cur[idx] + u;
        g_cur[idx] = nc;
        split_store(nc, g_curh, g_curl, idx);
    }
}

// ---------------- launcher ----------------
extern "C" void kernel_launch(void* const* d_in, const int* in_sizes, int n_in,
                              void* d_out, int out_size)
{
    const float* x      = (const float*)d_in[0];
    const float* W_qkv  = (const float*)d_in[1];
    const float* b_qkv  = (const float*)d_in[2];
    const float* W_pinv = (const float*)d_in[3];
    const float* b_pinv = (const float*)d_in[4];
    const float* W_attn = (const float*)d_in[5];
    const float* b_attn = (const float*)d_in[6];
    const float* W_out  = (const float*)d_in[7];
    const float* b_out  = (const float*)d_in[8];
    float* out = (float*)d_out;

    const int SM1 = 3 * 2 * 128 * 80;   // 61440 (gemm_qkv, 3-stage 128x128)
    const int SM3 = 2 * 4 * 128 * 80;   // 81920 (gemm3, 2-stage)
    const int SMF = 106496;             // flash (2 CTAs/SM)
    cudaFuncSetAttribute(gemm_qkv_kernel, cudaFuncAttributeMaxDynamicSharedMemorySize, SM1);
    cudaFuncSetAttribute(gemm3_kernel,    cudaFuncAttributeMaxDynamicSharedMemorySize, SM3);
    cudaFuncSetAttribute(flash_kernel,    cudaFuncAttributeMaxDynamicSharedMemorySize, SMF);

    __nv_bfloat16 *curh = nullptr, *curl = nullptr, *wqh = nullptr, *wql = nullptr,
                  *woh = nullptr, *wol = nullptr;
    cudaGetSymbolAddress((void**)&curh, g_curh);
    cudaGetSymbolAddress((void**)&curl, g_curl);
    cudaGetSymbolAddress((void**)&wqh,  g_Wqh);
    cudaGetSymbolAddress((void**)&wql,  g_Wql);
    cudaGetSymbolAddress((void**)&woh,  g_Woh);
    cudaGetSymbolAddress((void**)&wol,  g_Wol);

    copy_x_kernel<<<(M_ * HID_) / 4 / 256, 256>>>(x);
    wt_kernel<<<dim3(3 * HID_ / 32, HID_ / 32), dim3(32, 8)>>>(W_qkv, wqh, wql, HID_, 3 * HID_);
    wt_kernel<<<dim3(HID_ / 32, HID_ / 32), dim3(32, 8)>>>(W_out, woh, wol, HID_, HID_);

    for (int l = 0; l < L_; ++l) {
        gemm_qkv_kernel<<<dim3(24, 64), 128, SM1>>>(curh, wqh, b_qkv);
        flash_kernel<<<dim3(8, BH_), 256, SMF>>>(W_pinv);
        update_kernel<<<M_, 256>>>(b_pinv,
                                   W_attn + (size_t)l * MD_ * HID_,
                                   b_attn + (size_t)l * HID_);
    }

    gemm3_kernel<<<dim3(HID_ / 128, M_ / 128), 256, SM3>>>(
        curh, curl, woh, wol, b_out, out, HID_, HID_);
}